// round 1
// baseline (speedup 1.0000x reference)
#include <cuda_runtime.h>

#define NN 50000
#define EE 800000

// ---------------- scratch (device globals; no allocation allowed) ----------------
__device__ float g_dinv[NN];
__device__ int   g_indeg[NN];
__device__ int   g_cur[NN];
__device__ int   g_off[NN + 1];
__device__ int   g_adj[EE];
__device__ int   g_bsum[64];

__device__ float g_y0[NN * 64];     // dinv * x
__device__ float g_ax[NN * 64];     // A_norm x
__device__ float g_raw1[NN * 128];  // [mu64 | ls64] gcn1 out
__device__ float g_y1[NN * 128];    // dinv * act
__device__ float g_agg1[NN * 128];
__device__ float g_raw2[NN * 256];  // [mu128 | ls128]
__device__ float g_h2[NN * 256];
__device__ float g_y3[NN * 64];     // dinv * (h2 @ W3) [mu32 | ls32]
__device__ float g_agg3[NN * 64];

__device__ float g_ssum[512];
__device__ float g_ssq[512];
__device__ float g_mean[512];
__device__ float g_rstd[512];

// ---------------- setup ----------------
__global__ void k_zero() {
    int i = blockIdx.x * blockDim.x + threadIdx.x;
    if (i < NN) { g_indeg[i] = 0; g_cur[i] = 0; }
    if (i < 512) { g_ssum[i] = 0.f; g_ssq[i] = 0.f; }
}

__global__ void k_indeg(const int* __restrict__ dst) {
    int e = blockIdx.x * blockDim.x + threadIdx.x;
    if (e < EE) atomicAdd(&g_indeg[dst[e]], 1);
}

__global__ void k_dinv() {
    int i = blockIdx.x * blockDim.x + threadIdx.x;
    if (i < NN) g_dinv[i] = rsqrtf((float)(g_indeg[i] + 1));
}

__global__ void k_y0(const float* __restrict__ x) {
    int idx = blockIdx.x * blockDim.x + threadIdx.x;  // float4 units, NN*16 total
    if (idx < NN * 16) {
        int row = idx >> 4;
        float4 v = ((const float4*)x)[idx];
        float d = g_dinv[row];
        v.x *= d; v.y *= d; v.z *= d; v.w *= d;
        ((float4*)g_y0)[idx] = v;
    }
}

// ---------------- CSR build: scan + scatter ----------------
__global__ void k_scan1() {  // 49 blocks x 1024
    int i = blockIdx.x * 1024 + threadIdx.x;
    int v = (i < NN) ? g_indeg[i] : 0;
    int lane = threadIdx.x & 31, wid = threadIdx.x >> 5;
    int s = v;
    #pragma unroll
    for (int o = 1; o < 32; o <<= 1) {
        int t = __shfl_up_sync(~0u, s, o);
        if (lane >= o) s += t;
    }
    __shared__ int wsum[32];
    if (lane == 31) wsum[wid] = s;
    __syncthreads();
    if (wid == 0) {
        int ws = wsum[lane];
        #pragma unroll
        for (int o = 1; o < 32; o <<= 1) {
            int t = __shfl_up_sync(~0u, ws, o);
            if (lane >= o) ws += t;
        }
        wsum[lane] = ws;
    }
    __syncthreads();
    int incl = s + (wid > 0 ? wsum[wid - 1] : 0);
    if (i < NN) g_off[i + 1] = incl;
    if (threadIdx.x == 1023) g_bsum[blockIdx.x] = incl;
}

__global__ void k_scan2() {
    if (threadIdx.x == 0) {
        int acc = 0;
        for (int b = 0; b < 49; b++) { int t = g_bsum[b]; g_bsum[b] = acc; acc += t; }
    }
}

__global__ void k_scan3() {  // same grid as k_scan1
    int i = blockIdx.x * 1024 + threadIdx.x;
    if (i < NN) g_off[i + 1] += g_bsum[blockIdx.x];
    if (i == 0) g_off[0] = 0;
}

__global__ void k_scatter(const int* __restrict__ src, const int* __restrict__ dst) {
    int e = blockIdx.x * blockDim.x + threadIdx.x;
    if (e < EE) {
        int d = dst[e];
        int p = g_off[d] + atomicAdd(&g_cur[d], 1);
        g_adj[p] = src[e];
    }
}

// ---------------- aggregation: one warp per node ----------------
template <int W>
__global__ void k_agg(const float* __restrict__ y, float* __restrict__ out) {
    int gw = (blockIdx.x * blockDim.x + threadIdx.x) >> 5;
    if (gw >= NN) return;
    int lane = threadIdx.x & 31;
    int beg = g_off[gw], end = g_off[gw + 1];
    if (W == 64) {
        float2 acc = *(const float2*)(y + gw * 64 + lane * 2);
        for (int j = beg; j < end; j++) {
            int s = g_adj[j];
            float2 v = __ldg((const float2*)(y + s * 64 + lane * 2));
            acc.x += v.x; acc.y += v.y;
        }
        float d = g_dinv[gw];
        acc.x *= d; acc.y *= d;
        *(float2*)(out + gw * 64 + lane * 2) = acc;
    } else {
        float4 acc = *(const float4*)(y + gw * 128 + lane * 4);
        for (int j = beg; j < end; j++) {
            int s = g_adj[j];
            float4 v = __ldg((const float4*)(y + s * 128 + lane * 4));
            acc.x += v.x; acc.y += v.y; acc.z += v.z; acc.w += v.w;
        }
        float d = g_dinv[gw];
        acc.x *= d; acc.y *= d; acc.z *= d; acc.w *= d;
        *(float4*)(out + gw * 128 + lane * 4) = acc;
    }
}

// ---------------- GEMM: C[N,NO] = A[N,NI] @ W[NI,NO] (+bias) (*dinv) ----------------
template <int NI, int NO>
__global__ void k_gemm(const float* __restrict__ A, int lda,
                       const float* __restrict__ Wt, const float* __restrict__ bias,
                       float* __restrict__ C, int ldc, int scale_dinv) {
    __shared__ float Ws[NI * NO];
    __shared__ float As[64 * 32];
    int tid = threadIdx.x;  // 256
    int row0 = blockIdx.x * 64;

    for (int i = tid; i < NI * NO / 4; i += 256)
        ((float4*)Ws)[i] = ((const float4*)Wt)[i];

    int tx = tid & 31, ty = tid >> 5;  // ty: 0..7
    const int CPT = NO / 32;
    float acc[8][CPT > 0 ? CPT : 1];
    #pragma unroll
    for (int i = 0; i < 8; i++)
        #pragma unroll
        for (int j = 0; j < CPT; j++) acc[i][j] = 0.f;

    for (int kt = 0; kt < NI; kt += 32) {
        __syncthreads();
        // load 64x32 A tile (512 float4)
        for (int i = tid; i < 512; i += 256) {
            int r = i >> 3, kk = i & 7;
            float4 v = make_float4(0.f, 0.f, 0.f, 0.f);
            if (row0 + r < NN)
                v = *(const float4*)(A + (row0 + r) * lda + kt + kk * 4);
            ((float4*)As)[i] = v;
        }
        __syncthreads();
        #pragma unroll 8
        for (int k = 0; k < 32; k++) {
            float wv[CPT > 0 ? CPT : 1];
            #pragma unroll
            for (int j = 0; j < CPT; j++) wv[j] = Ws[(kt + k) * NO + tx + 32 * j];
            #pragma unroll
            for (int i = 0; i < 8; i++) {
                float a = As[(ty * 8 + i) * 32 + k];
                #pragma unroll
                for (int j = 0; j < CPT; j++) acc[i][j] += a * wv[j];
            }
        }
    }
    #pragma unroll
    for (int i = 0; i < 8; i++) {
        int r = row0 + ty * 8 + i;
        if (r >= NN) break;
        float s = scale_dinv ? g_dinv[r] : 1.0f;
        #pragma unroll
        for (int j = 0; j < CPT; j++) {
            int col = tx + 32 * j;
            float v = acc[i][j];
            if (bias) v += bias[col];
            C[r * ldc + col] = v * s;
        }
    }
}

// ---------------- BN stats (relu-first applied to cols >= MUC) ----------------
template <int C, int MUC>
__global__ void k_stats(const float* __restrict__ X, int base) {
    int c = threadIdx.x;  // blockDim == C
    int r0 = blockIdx.x * 256;
    int rend = r0 + 256 < NN ? r0 + 256 : NN;
    float s = 0.f, s2 = 0.f;
    for (int r = r0; r < rend; r++) {
        float v = X[r * C + c];
        if (c >= MUC) v = fmaxf(v, 0.f);
        s += v; s2 += v * v;
    }
    atomicAdd(&g_ssum[base + c], s);
    atomicAdd(&g_ssq[base + c], s2);
}

__global__ void k_stat_fin(int base, int C) {
    int c = blockIdx.x * blockDim.x + threadIdx.x;
    if (c < C) {
        float m = g_ssum[base + c] * (1.0f / NN);
        float v = g_ssq[base + c] * (1.0f / NN) - m * m;
        g_mean[base + c] = m;
        g_rstd[base + c] = rsqrtf(v + 1e-5f);
    }
}

// ---------------- elementwise ----------------
// layer1: cols 0..63 mu (relu after BN), 64..127 logstd (BN after relu); *dinv
__global__ void k_ew1(const float* __restrict__ gm, const float* __restrict__ hm,
                      const float* __restrict__ gl, const float* __restrict__ hl) {
    int idx = blockIdx.x * blockDim.x + threadIdx.x;  // NN*128
    int c = idx & 127, r = idx >> 7;
    float v = g_raw1[idx];
    float m = g_mean[c], rs = g_rstd[c];
    float o;
    if (c < 64) {
        o = fmaxf((v - m) * rs * gm[c] + hm[c], 0.f);
    } else {
        float t = fmaxf(v, 0.f);
        o = (t - m) * rs * gl[c - 64] + hl[c - 64];
    }
    g_y1[idx] = o * g_dinv[r];
}

// layer2: cols 0..127 mu, 128..255 logstd; no dinv (matmul-first next layer)
__global__ void k_ew2(const float* __restrict__ gm, const float* __restrict__ hm,
                      const float* __restrict__ gl, const float* __restrict__ hl) {
    int idx = blockIdx.x * blockDim.x + threadIdx.x;  // NN*256
    int c = idx & 255;
    float v = g_raw2[idx];
    float m = g_mean[256 + c], rs = g_rstd[256 + c];
    float o;
    if (c < 128) {
        o = fmaxf((v - m) * rs * gm[c] + hm[c], 0.f);
    } else {
        float t = fmaxf(v, 0.f);
        o = (t - m) * rs * gl[c - 128] + hl[c - 128];
    }
    g_h2[idx] = o;
}

// final bias + clamp + write mu/logstd
__global__ void k_final(const float* __restrict__ bm3, const float* __restrict__ bl3,
                        float* __restrict__ out_mu, float* __restrict__ out_ls) {
    int idx = blockIdx.x * blockDim.x + threadIdx.x;  // NN*64
    int c = idx & 63, r = idx >> 6;
    float v = g_agg3[idx];
    if (c < 32)
        out_mu[r * 32 + c] = v + bm3[c];
    else
        out_ls[r * 32 + (c - 32)] = fminf(v + bl3[c - 32], 10.0f);
}

// ---------------- decoder: 8 lanes per edge ----------------
__global__ void k_dec(const int* __restrict__ src, const int* __restrict__ dst,
                      const float* __restrict__ mu, float* __restrict__ probs) {
    int t = blockIdx.x * blockDim.x + threadIdx.x;  // EE*8 exactly
    int e = t >> 3, sub = t & 7;
    int s = src[e], d = dst[e];
    float4 a = __ldg((const float4*)(mu + s * 32 + sub * 4));
    float4 b = __ldg((const float4*)(mu + d * 32 + sub * 4));
    float p = a.x * b.x + a.y * b.y + a.z * b.z + a.w * b.w;
    p += __shfl_down_sync(~0u, p, 4);
    p += __shfl_down_sync(~0u, p, 2);
    p += __shfl_down_sync(~0u, p, 1);
    if (sub == 0) probs[e] = 1.f / (1.f + expf(-p));
}

// ---------------- launch ----------------
extern "C" void kernel_launch(void* const* d_in, const int* in_sizes, int n_in,
                              void* d_out, int out_size) {
    const float* x   = (const float*)d_in[0];
    const int* ei    = (const int*)d_in[1];
    const int* src   = ei;
    const int* dst   = ei + EE;
    const float* Wm1 = (const float*)d_in[2];
    const float* bm1 = (const float*)d_in[3];
    const float* gm1 = (const float*)d_in[4];
    const float* hm1 = (const float*)d_in[5];
    const float* Wm2 = (const float*)d_in[6];
    const float* bm2 = (const float*)d_in[7];
    const float* gm2 = (const float*)d_in[8];
    const float* hm2 = (const float*)d_in[9];
    const float* Wm3 = (const float*)d_in[10];
    const float* bm3 = (const float*)d_in[11];
    const float* Wl1 = (const float*)d_in[12];
    const float* bl1 = (const float*)d_in[13];
    const float* gl1 = (const float*)d_in[14];
    const float* hl1 = (const float*)d_in[15];
    const float* Wl2 = (const float*)d_in[16];
    const float* bl2 = (const float*)d_in[17];
    const float* gl2 = (const float*)d_in[18];
    const float* hl2 = (const float*)d_in[19];
    const float* Wl3 = (const float*)d_in[20];
    const float* bl3 = (const float*)d_in[21];

    float* out = (float*)d_out;
    float* out_probs = out;
    float* out_mu = out + EE;
    float* out_ls = out + EE + NN * 32;

    float *y0, *ax, *raw1, *y1, *agg1, *raw2, *h2, *y3, *agg3;
    cudaGetSymbolAddress((void**)&y0, g_y0);
    cudaGetSymbolAddress((void**)&ax, g_ax);
    cudaGetSymbolAddress((void**)&raw1, g_raw1);
    cudaGetSymbolAddress((void**)&y1, g_y1);
    cudaGetSymbolAddress((void**)&agg1, g_agg1);
    cudaGetSymbolAddress((void**)&raw2, g_raw2);
    cudaGetSymbolAddress((void**)&h2, g_h2);
    cudaGetSymbolAddress((void**)&y3, g_y3);
    cudaGetSymbolAddress((void**)&agg3, g_agg3);

    // setup + degree
    k_zero<<<196, 256>>>();
    k_indeg<<<3125, 256>>>(dst);
    k_dinv<<<196, 256>>>();
    k_y0<<<3125, 256>>>(x);

    // CSR build
    k_scan1<<<49, 1024>>>();
    k_scan2<<<1, 32>>>();
    k_scan3<<<49, 1024>>>();
    k_scatter<<<3125, 256>>>(src, dst);

    // ---- layer 1: aggregate x (width 64), then two 64->64 matmuls ----
    k_agg<64><<<6250, 256>>>(y0, ax);
    k_gemm<64, 64><<<782, 256>>>(ax, 64, Wm1, bm1, raw1, 128, 0);
    k_gemm<64, 64><<<782, 256>>>(ax, 64, Wl1, bl1, raw1 + 64, 128, 0);
    k_stats<128, 64><<<196, 128>>>(raw1, 0);
    k_stat_fin<<<1, 128>>>(0, 128);
    k_ew1<<<25000, 256>>>(gm1, hm1, gl1, hl1);

    // ---- layer 2: aggregate (width 128), two 64->128 matmuls ----
    k_agg<128><<<6250, 256>>>(y1, agg1);
    k_gemm<64, 128><<<782, 256>>>(agg1, 128, Wm2, bm2, raw2, 256, 0);
    k_gemm<64, 128><<<782, 256>>>(agg1 + 64, 128, Wl2, bl2, raw2 + 128, 256, 0);
    k_stats<256, 128><<<196, 256>>>(raw2, 256);
    k_stat_fin<<<1, 256>>>(256, 256);
    k_ew2<<<50000, 256>>>(gm2, hm2, gl2, hl2);

    // ---- layer 3: two 128->32 matmuls (scaled by dinv), aggregate (width 64) ----
    k_gemm<128, 32><<<782, 256>>>(h2, 256, Wm3, nullptr, y3, 64, 1);
    k_gemm<128, 32><<<782, 256>>>(h2 + 128, 256, Wl3, nullptr, y3 + 32, 64, 1);
    k_agg<64><<<6250, 256>>>(y3, agg3);
    k_final<<<12500, 256>>>(bm3, bl3, out_mu, out_ls);

    // ---- decoder ----
    k_dec<<<25000, 256>>>(src, dst, out_mu, out_probs);
}

// round 2
// speedup vs baseline: 1.2614x; 1.2614x over previous
#include <cuda_runtime.h>

#define NN 50000
#define EE 800000

// ---------------- scratch (device globals; no allocation allowed) ----------------
__device__ float g_dinv[NN];
__device__ int   g_indeg[NN];
__device__ int   g_cur[NN];
__device__ int   g_off[NN + 1];
__device__ int   g_adj[EE];
__device__ int   g_bsum[64];

__device__ float g_y0[NN * 64];     // dinv * x
__device__ float g_ax[NN * 64];     // A_norm x
__device__ float g_raw1[NN * 128];  // [mu64 | ls64] gcn1 linear out
__device__ float g_y1[NN * 128];    // dinv * act1
__device__ float g_agg1[NN * 128];  // aggregated act1
__device__ float g_raw2[NN * 256];  // [mu128 | ls128] gcn2 linear out
__device__ float g_y3[NN * 64];     // dinv * (act2 @ W3)  [mu32 | ls32]

__device__ float g_ssum[512];
__device__ float g_ssq[512];
__device__ float g_bna[512];   // folded BN scale  = gamma * rstd
__device__ float g_bnb[512];   // folded BN shift  = beta - mean * gamma * rstd

// ---------------- setup ----------------
__global__ void k_zero() {
    int i = blockIdx.x * blockDim.x + threadIdx.x;
    if (i < NN) { g_indeg[i] = 0; g_cur[i] = 0; }
    if (i < 512) { g_ssum[i] = 0.f; g_ssq[i] = 0.f; }
}

__global__ void k_indeg(const int* __restrict__ dst) {
    int e = blockIdx.x * blockDim.x + threadIdx.x;
    if (e < EE) atomicAdd(&g_indeg[dst[e]], 1);
}

// dinv + y0 = dinv*x fused. grid covers NN*16 float4s.
__global__ void k_dinv_y0(const float* __restrict__ x) {
    int idx = blockIdx.x * blockDim.x + threadIdx.x;
    if (idx < NN * 16) {
        int row = idx >> 4;
        float d = rsqrtf((float)(g_indeg[row] + 1));
        if ((idx & 15) == 0) g_dinv[row] = d;
        float4 v = ((const float4*)x)[idx];
        v.x *= d; v.y *= d; v.z *= d; v.w *= d;
        ((float4*)g_y0)[idx] = v;
    }
}

// ---------------- CSR build: scan + scatter ----------------
__global__ void k_scan1() {  // 49 blocks x 1024
    int i = blockIdx.x * 1024 + threadIdx.x;
    int v = (i < NN) ? g_indeg[i] : 0;
    int lane = threadIdx.x & 31, wid = threadIdx.x >> 5;
    int s = v;
    #pragma unroll
    for (int o = 1; o < 32; o <<= 1) {
        int t = __shfl_up_sync(~0u, s, o);
        if (lane >= o) s += t;
    }
    __shared__ int wsum[32];
    if (lane == 31) wsum[wid] = s;
    __syncthreads();
    if (wid == 0) {
        int ws = wsum[lane];
        #pragma unroll
        for (int o = 1; o < 32; o <<= 1) {
            int t = __shfl_up_sync(~0u, ws, o);
            if (lane >= o) ws += t;
        }
        wsum[lane] = ws;
    }
    __syncthreads();
    int incl = s + (wid > 0 ? wsum[wid - 1] : 0);
    if (i < NN) g_off[i + 1] = incl;
    if (threadIdx.x == 1023) g_bsum[blockIdx.x] = incl;
}

__global__ void k_scan2() {
    if (threadIdx.x == 0) {
        int acc = 0;
        for (int b = 0; b < 49; b++) { int t = g_bsum[b]; g_bsum[b] = acc; acc += t; }
    }
}

__global__ void k_scan3() {
    int i = blockIdx.x * 1024 + threadIdx.x;
    if (i < NN) g_off[i + 1] += g_bsum[blockIdx.x];
    if (i == 0) g_off[0] = 0;
}

__global__ void k_scatter(const int* __restrict__ src, const int* __restrict__ dst) {
    int e = blockIdx.x * blockDim.x + threadIdx.x;
    if (e < EE) {
        int d = dst[e];
        int p = g_off[d] + atomicAdd(&g_cur[d], 1);
        g_adj[p] = src[e];
    }
}

// ---------------- aggregation: one warp per node ----------------
// MODE 0: plain write W-wide. MODE 1 (W=64): final epilogue (bias, clamp, split)
template <int W, int MODE>
__global__ void k_agg(const float* __restrict__ y, float* __restrict__ out,
                      const float* __restrict__ bm3, const float* __restrict__ bl3,
                      float* __restrict__ out_ls) {
    int gw = (blockIdx.x * blockDim.x + threadIdx.x) >> 5;
    if (gw >= NN) return;
    int lane = threadIdx.x & 31;
    int beg = g_off[gw], end = g_off[gw + 1];
    if (W == 64) {
        float2 acc = *(const float2*)(y + gw * 64 + lane * 2);
        for (int j = beg; j < end; j++) {
            int s = g_adj[j];
            float2 v = __ldg((const float2*)(y + s * 64 + lane * 2));
            acc.x += v.x; acc.y += v.y;
        }
        float d = g_dinv[gw];
        acc.x *= d; acc.y *= d;
        if (MODE == 0) {
            *(float2*)(out + gw * 64 + lane * 2) = acc;
        } else {
            int c = lane * 2;
            if (c < 32) {
                out[gw * 32 + c]     = acc.x + bm3[c];
                out[gw * 32 + c + 1] = acc.y + bm3[c + 1];
            } else {
                out_ls[gw * 32 + c - 32] = fminf(acc.x + bl3[c - 32], 10.0f);
                out_ls[gw * 32 + c - 31] = fminf(acc.y + bl3[c - 31], 10.0f);
            }
        }
    } else {
        float4 acc = *(const float4*)(y + gw * 128 + lane * 4);
        for (int j = beg; j < end; j++) {
            int s = g_adj[j];
            float4 v = __ldg((const float4*)(y + s * 128 + lane * 4));
            acc.x += v.x; acc.y += v.y; acc.z += v.z; acc.w += v.w;
        }
        float d = g_dinv[gw];
        acc.x *= d; acc.y *= d; acc.z *= d; acc.w *= d;
        *(float4*)(out + gw * 128 + lane * 4) = acc;
    }
}

// ---------------- layer-1 fused GEMM: raw1[:,0:64]=ax@Wm1+bm1, [:,64:128]=ax@Wl1+bl1
// + BN stats (cols>=64 get relu before stats). 64 rows/block, 256 threads.
__global__ void __launch_bounds__(256) k_gemm1(
        const float* __restrict__ A, const float* __restrict__ W1,
        const float* __restrict__ W2, const float* __restrict__ b1,
        const float* __restrict__ b2, float* __restrict__ C) {
    __shared__ float Ws[64 * 128];   // 32KB  [k][c]  c<64: W1, c>=64: W2
    __shared__ float As[64 * 64];    // 16KB
    int tid = threadIdx.x;
    int row0 = blockIdx.x * 64;

    for (int i = tid; i < 1024; i += 256) {
        int k = i >> 4, q = i & 15;
        ((float4*)(Ws + k * 128))[q]      = ((const float4*)(W1 + k * 64))[q];
        ((float4*)(Ws + k * 128 + 64))[q] = ((const float4*)(W2 + k * 64))[q];
    }
    for (int i = tid; i < 1024; i += 256) {
        int r = i >> 4, q = i & 15;
        float4 v = make_float4(0.f, 0.f, 0.f, 0.f);
        if (row0 + r < NN) v = ((const float4*)(A + (row0 + r) * 64))[q];
        ((float4*)(As + r * 64))[q] = v;
    }
    __syncthreads();

    int tx = tid & 31, ty = tid >> 5;
    float acc[8][4];
    #pragma unroll
    for (int i = 0; i < 8; i++)
        #pragma unroll
        for (int j = 0; j < 4; j++) acc[i][j] = 0.f;

    #pragma unroll 8
    for (int k = 0; k < 64; k++) {
        float w0 = Ws[k * 128 + tx], w1 = Ws[k * 128 + tx + 32];
        float w2 = Ws[k * 128 + tx + 64], w3 = Ws[k * 128 + tx + 96];
        #pragma unroll
        for (int i = 0; i < 8; i++) {
            float a = As[(ty * 8 + i) * 64 + k];
            acc[i][0] += a * w0; acc[i][1] += a * w1;
            acc[i][2] += a * w2; acc[i][3] += a * w3;
        }
    }

    float bb[4];
    bb[0] = b1[tx]; bb[1] = b1[tx + 32]; bb[2] = b2[tx]; bb[3] = b2[tx + 32];

    float ls[4] = {0.f, 0.f, 0.f, 0.f}, l2[4] = {0.f, 0.f, 0.f, 0.f};
    #pragma unroll
    for (int i = 0; i < 8; i++) {
        int r = row0 + ty * 8 + i;
        if (r < NN) {
            #pragma unroll
            for (int j = 0; j < 4; j++) {
                float v = acc[i][j] + bb[j];
                C[(size_t)r * 128 + tx + 32 * j] = v;
                float sv = (j < 2) ? v : fmaxf(v, 0.f);   // ls branch: relu before BN
                ls[j] += sv; l2[j] += sv * sv;
            }
        }
    }
    // reduce stats: alias As as 256-float scratch
    __syncthreads();
    float* red = As;
    red[tid] = 0.f;
    __syncthreads();
    #pragma unroll
    for (int j = 0; j < 4; j++) {
        atomicAdd(&red[tx + 32 * j], ls[j]);
        atomicAdd(&red[128 + tx + 32 * j], l2[j]);
    }
    __syncthreads();
    if (tid < 128) {
        atomicAdd(&g_ssum[tid], red[tid]);
        atomicAdd(&g_ssq[tid], red[tid + 128]);
    }
}

// finalize stats -> folded scale/shift
__global__ void k_statfin(int base, int C, const float* __restrict__ g1,
                          const float* __restrict__ h1, const float* __restrict__ g2,
                          const float* __restrict__ h2, int half) {
    int c = threadIdx.x;
    if (c < C) {
        float m = g_ssum[base + c] * (1.0f / NN);
        float v = g_ssq[base + c] * (1.0f / NN) - m * m;
        float rstd = rsqrtf(v + 1e-5f);
        float gamma = (c < half) ? g1[c] : g2[c - half];
        float beta  = (c < half) ? h1[c] : h2[c - half];
        float a = gamma * rstd;
        g_bna[base + c] = a;
        g_bnb[base + c] = beta - m * a;
    }
}

// elementwise layer1: apply BN/ReLU (order per branch), scale by dinv. float4.
__global__ void k_ew1() {
    int idx = blockIdx.x * blockDim.x + threadIdx.x;  // NN*32 float4s
    if (idx >= NN * 32) return;
    int r = idx >> 5;
    int c4 = (idx & 31) << 2;
    float4 v = ((const float4*)g_raw1)[idx];
    float d = g_dinv[r];
    float o[4]; float vv[4] = {v.x, v.y, v.z, v.w};
    #pragma unroll
    for (int t = 0; t < 4; t++) {
        int c = c4 + t;
        float a = g_bna[c], b = g_bnb[c];
        if (c4 < 64) o[t] = fmaxf(vv[t] * a + b, 0.f);       // mu: BN then relu
        else         o[t] = fmaxf(vv[t], 0.f) * a + b;       // ls: relu then BN
        o[t] *= d;
    }
    ((float4*)g_y1)[idx] = make_float4(o[0], o[1], o[2], o[3]);
}

// ---------------- layer-2 fused GEMM: raw2[:,0:128]=agg1[:,0:64]@Wm2+bm2,
//                  raw2[:,128:256]=agg1[:,64:128]@Wl2+bl2, + stats. dyn smem 96KB.
__global__ void __launch_bounds__(256) k_gemm2(
        const float* __restrict__ A, const float* __restrict__ W1,
        const float* __restrict__ W2, const float* __restrict__ b1,
        const float* __restrict__ b2, float* __restrict__ C) {
    extern __shared__ float sm2[];
    float* Ws = sm2;            // 64*256
    float* As = sm2 + 64 * 256; // 64*128
    int tid = threadIdx.x;
    int row0 = blockIdx.x * 64;

    for (int i = tid; i < 2048; i += 256) {
        int k = i >> 5, q = i & 31;
        ((float4*)(Ws + k * 256))[q]       = ((const float4*)(W1 + k * 128))[q];
        ((float4*)(Ws + k * 256 + 128))[q] = ((const float4*)(W2 + k * 128))[q];
    }
    for (int i = tid; i < 2048; i += 256) {
        int r = i >> 5, q = i & 31;
        float4 v = make_float4(0.f, 0.f, 0.f, 0.f);
        if (row0 + r < NN) v = ((const float4*)(A + (size_t)(row0 + r) * 128))[q];
        ((float4*)(As + r * 128))[q] = v;
    }
    __syncthreads();

    int tx = tid & 31, ty = tid >> 5;
    float acc[8][8];
    #pragma unroll
    for (int i = 0; i < 8; i++)
        #pragma unroll
        for (int j = 0; j < 8; j++) acc[i][j] = 0.f;

    #pragma unroll 4
    for (int k = 0; k < 64; k++) {
        float w[8];
        #pragma unroll
        for (int j = 0; j < 8; j++) w[j] = Ws[k * 256 + tx + 32 * j];
        #pragma unroll
        for (int i = 0; i < 8; i++) {
            float alo = As[(ty * 8 + i) * 128 + k];
            float ahi = As[(ty * 8 + i) * 128 + 64 + k];
            #pragma unroll
            for (int j = 0; j < 8; j++)
                acc[i][j] += (j < 4 ? alo : ahi) * w[j];
        }
    }

    float bb[8];
    #pragma unroll
    for (int j = 0; j < 8; j++)
        bb[j] = (j < 4) ? b1[tx + 32 * j] : b2[tx + 32 * j - 128];

    float ls[8], l2[8];
    #pragma unroll
    for (int j = 0; j < 8; j++) { ls[j] = 0.f; l2[j] = 0.f; }
    #pragma unroll
    for (int i = 0; i < 8; i++) {
        int r = row0 + ty * 8 + i;
        if (r < NN) {
            #pragma unroll
            for (int j = 0; j < 8; j++) {
                float v = acc[i][j] + bb[j];
                C[(size_t)r * 256 + tx + 32 * j] = v;
                float sv = (j < 4) ? v : fmaxf(v, 0.f);
                ls[j] += sv; l2[j] += sv * sv;
            }
        }
    }
    __syncthreads();
    float* red = As;   // 512 floats scratch
    red[tid] = 0.f; red[tid + 256] = 0.f;
    __syncthreads();
    #pragma unroll
    for (int j = 0; j < 8; j++) {
        atomicAdd(&red[tx + 32 * j], ls[j]);
        atomicAdd(&red[256 + tx + 32 * j], l2[j]);
    }
    __syncthreads();
    atomicAdd(&g_ssum[256 + tid], red[tid]);
    atomicAdd(&g_ssq[256 + tid], red[tid + 256]);
}

// ---------------- layer-3 fused GEMM with BN-on-load:
// y3[:,0:32] = bnrelu_mu(raw2[:,0:128]) @ Wm3 * dinv
// y3[:,32:64]= bnrelu_ls(raw2[:,128:256]) @ Wl3 * dinv.  128 rows/block. dyn smem 64KB.
__global__ void __launch_bounds__(256) k_gemm3(
        const float* __restrict__ raw2, const float* __restrict__ Wm3,
        const float* __restrict__ Wl3, float* __restrict__ y3) {
    extern __shared__ float sm3[];
    float* Ws = sm3;             // 128*64  [k][c] c<32 mu, c>=32 ls
    float* As = sm3 + 128 * 64;  // 128 rows * (2 halves * 32 k)
    int tid = threadIdx.x;
    int row0 = blockIdx.x * 128;

    for (int i = tid; i < 2048; i += 256) {
        int k = i >> 4, q = i & 15;
        float4 v = (q < 8) ? ((const float4*)(Wm3 + k * 32))[q]
                           : ((const float4*)(Wl3 + k * 32))[q - 8];
        ((float4*)(Ws + k * 64))[q] = v;
    }

    int tx = tid & 15, ty = tid >> 4;    // tx: 4 cols, ty: 8 rows
    int half_c = (tx >= 8) ? 1 : 0;
    float acc[8][4];
    #pragma unroll
    for (int i = 0; i < 8; i++)
        #pragma unroll
        for (int j = 0; j < 4; j++) acc[i][j] = 0.f;

    for (int kt = 0; kt < 128; kt += 32) {
        __syncthreads();
        // load + BN-transform A tile: 128 rows x {2 halves x 32 k}
        for (int i = tid; i < 2048; i += 256) {
            int r = i >> 4, q = i & 15;
            int half = q >> 3, kk = (q & 7) << 2;
            float4 v = make_float4(0.f, 0.f, 0.f, 0.f);
            if (row0 + r < NN)
                v = ((const float4*)(raw2 + (size_t)(row0 + r) * 256 + half * 128 + kt))[q & 7];
            float o[4]; float vv[4] = {v.x, v.y, v.z, v.w};
            #pragma unroll
            for (int t = 0; t < 4; t++) {
                int col = 256 + half * 128 + kt + kk + t;
                float a = g_bna[col], b = g_bnb[col];
                if (half == 0) o[t] = fmaxf(vv[t] * a + b, 0.f);
                else           o[t] = fmaxf(vv[t], 0.f) * a + b;
            }
            ((float4*)(As + r * 64 + half * 32))[(kk >> 2)] =
                make_float4(o[0], o[1], o[2], o[3]);
        }
        __syncthreads();
        #pragma unroll 8
        for (int k = 0; k < 32; k++) {
            float4 w = ((float4*)(Ws + (kt + k) * 64))[tx];
            #pragma unroll
            for (int i = 0; i < 8; i++) {
                float a = As[(ty * 8 + i) * 64 + half_c * 32 + k];
                acc[i][0] += a * w.x; acc[i][1] += a * w.y;
                acc[i][2] += a * w.z; acc[i][3] += a * w.w;
            }
        }
    }
    #pragma unroll
    for (int i = 0; i < 8; i++) {
        int r = row0 + ty * 8 + i;
        if (r < NN) {
            float d = g_dinv[r];
            float4 o = make_float4(acc[i][0] * d, acc[i][1] * d, acc[i][2] * d, acc[i][3] * d);
            ((float4*)(y3 + (size_t)r * 64))[tx] = o;
        }
    }
}

// ---------------- decoder: 8 lanes per edge ----------------
__global__ void k_dec(const int* __restrict__ src, const int* __restrict__ dst,
                      const float* __restrict__ mu, float* __restrict__ probs) {
    int t = blockIdx.x * blockDim.x + threadIdx.x;  // EE*8 exactly
    int e = t >> 3, sub = t & 7;
    int s = src[e], d = dst[e];
    float4 a = __ldg((const float4*)(mu + s * 32 + sub * 4));
    float4 b = __ldg((const float4*)(mu + d * 32 + sub * 4));
    float p = a.x * b.x + a.y * b.y + a.z * b.z + a.w * b.w;
    p += __shfl_down_sync(~0u, p, 4);
    p += __shfl_down_sync(~0u, p, 2);
    p += __shfl_down_sync(~0u, p, 1);
    if (sub == 0) probs[e] = 1.f / (1.f + expf(-p));
}

// ---------------- launch ----------------
extern "C" void kernel_launch(void* const* d_in, const int* in_sizes, int n_in,
                              void* d_out, int out_size) {
    const float* x   = (const float*)d_in[0];
    const int* ei    = (const int*)d_in[1];
    const int* src   = ei;
    const int* dst   = ei + EE;
    const float* Wm1 = (const float*)d_in[2];
    const float* bm1 = (const float*)d_in[3];
    const float* gm1 = (const float*)d_in[4];
    const float* hm1 = (const float*)d_in[5];
    const float* Wm2 = (const float*)d_in[6];
    const float* bm2 = (const float*)d_in[7];
    const float* gm2 = (const float*)d_in[8];
    const float* hm2 = (const float*)d_in[9];
    const float* Wm3 = (const float*)d_in[10];
    const float* bm3 = (const float*)d_in[11];
    const float* Wl1 = (const float*)d_in[12];
    const float* bl1 = (const float*)d_in[13];
    const float* gl1 = (const float*)d_in[14];
    const float* hl1 = (const float*)d_in[15];
    const float* Wl2 = (const float*)d_in[16];
    const float* bl2 = (const float*)d_in[17];
    const float* gl2 = (const float*)d_in[18];
    const float* hl2 = (const float*)d_in[19];
    const float* Wl3 = (const float*)d_in[20];
    const float* bl3 = (const float*)d_in[21];

    float* out = (float*)d_out;
    float* out_probs = out;
    float* out_mu = out + EE;
    float* out_ls = out + EE + NN * 32;

    float *y0, *ax, *raw1, *y1, *agg1, *raw2, *y3;
    cudaGetSymbolAddress((void**)&y0, g_y0);
    cudaGetSymbolAddress((void**)&ax, g_ax);
    cudaGetSymbolAddress((void**)&raw1, g_raw1);
    cudaGetSymbolAddress((void**)&y1, g_y1);
    cudaGetSymbolAddress((void**)&agg1, g_agg1);
    cudaGetSymbolAddress((void**)&raw2, g_raw2);
    cudaGetSymbolAddress((void**)&y3, g_y3);

    cudaFuncSetAttribute(k_gemm2, cudaFuncAttributeMaxDynamicSharedMemorySize, 98304);
    cudaFuncSetAttribute(k_gemm3, cudaFuncAttributeMaxDynamicSharedMemorySize, 65536);

    // setup + degree + CSR
    k_zero<<<196, 256>>>();
    k_indeg<<<3125, 256>>>(dst);
    k_dinv_y0<<<3125, 256>>>(x);
    k_scan1<<<49, 1024>>>();
    k_scan2<<<1, 32>>>();
    k_scan3<<<49, 1024>>>();
    k_scatter<<<3125, 256>>>(src, dst);

    // layer 1
    k_agg<64, 0><<<6250, 256>>>(y0, ax, nullptr, nullptr, nullptr);
    k_gemm1<<<782, 256>>>(ax, Wm1, Wl1, bm1, bl1, raw1);
    k_statfin<<<1, 128>>>(0, 128, gm1, hm1, gl1, hl1, 64);
    k_ew1<<<6250, 256>>>();

    // layer 2
    k_agg<128, 0><<<6250, 256>>>(y1, agg1, nullptr, nullptr, nullptr);
    k_gemm2<<<782, 256, 98304>>>(agg1, Wm2, Wl2, bm2, bl2, raw2);
    k_statfin<<<1, 256>>>(256, 256, gm2, hm2, gl2, hl2, 128);

    // layer 3 (BN applied on load inside gemm3)
    k_gemm3<<<391, 256, 65536>>>(raw2, Wm3, Wl3, y3);
    k_agg<64, 1><<<6250, 256>>>(y3, out_mu, bm3, bl3, out_ls);

    // decoder
    k_dec<<<25000, 256>>>(src, dst, out_mu, out_probs);
}